// round 1
// baseline (speedup 1.0000x reference)
#include <cuda_runtime.h>

#define NSTATES 512
#define MSYMS   256
#define BATCHN  256
#define TLEN    256

#define GB 8                    // batch groups
#define GI 16                   // i-tiles
#define BC (BATCHN/GB)          // 32 batch rows per CTA
#define IC (NSTATES/GI)         // 32 states per CTA
#define NB (GB*GI)              // 128 CTAs (<=148 SMs -> all co-resident)
#define NT 256

#define PSTR 516                // padded SMEM strides (floats), conflict-free float4
#define ESTR 520

// ---------------- device globals (no allocations allowed) ----------------
__device__ float gP[NSTATES*NSTATES];      // exp(log_T) = column-softmax of transition
__device__ float gLET[MSYMS*NSTATES];      // log_E transposed: [sym][state]
__device__ float gLP[NSTATES];             // log priors
__device__ float gColLse[NSTATES];         // per-column lse of transition
__device__ float gE[2][BATCHN][NSTATES];   // exp(alpha - tile_max), double buffered
__device__ float gM[2][BATCHN][GI];        // per (b, i-tile) max
__device__ float gS[2][BATCHN][GI];        // per (b, i-tile) sum of exp
__device__ unsigned g_cnt;                 // grid barrier counter

// ---------------- prep kernels ----------------
__global__ void k_reset() { g_cnt = 0u; }

// row log-softmax of emission [N,M], stored transposed as gLET[m][n]
__global__ void k_prep_emission(const float* __restrict__ em) {
    __shared__ float red[MSYMS];
    int n = blockIdx.x, t = threadIdx.x;
    float x = em[n * MSYMS + t];
    red[t] = x; __syncthreads();
    for (int s = MSYMS/2; s > 0; s >>= 1) { if (t < s) red[t] = fmaxf(red[t], red[t+s]); __syncthreads(); }
    float m = red[0]; __syncthreads();
    red[t] = __expf(x - m); __syncthreads();
    for (int s = MSYMS/2; s > 0; s >>= 1) { if (t < s) red[t] += red[t+s]; __syncthreads(); }
    float lse = m + __logf(red[0]);
    gLET[t * NSTATES + n] = x - lse;
}

// per-column (axis 0) lse of transition
__global__ void k_prep_tstats(const float* __restrict__ tr) {
    __shared__ float red[256];
    int k = blockIdx.x, t = threadIdx.x;
    float x0 = tr[t * NSTATES + k];
    float x1 = tr[(t + 256) * NSTATES + k];
    red[t] = fmaxf(x0, x1); __syncthreads();
    for (int s = 128; s > 0; s >>= 1) { if (t < s) red[t] = fmaxf(red[t], red[t+s]); __syncthreads(); }
    float m = red[0]; __syncthreads();
    red[t] = __expf(x0 - m) + __expf(x1 - m); __syncthreads();
    for (int s = 128; s > 0; s >>= 1) { if (t < s) red[t] += red[t+s]; __syncthreads(); }
    if (t == 0) gColLse[k] = m + __logf(red[0]);
}

__global__ void k_prep_P(const float* __restrict__ tr) {
    int i = blockIdx.x, k = threadIdx.x;
    gP[i * NSTATES + k] = __expf(tr[i * NSTATES + k] - gColLse[k]);
}

__global__ void k_prep_priors(const float* __restrict__ pr) {
    __shared__ float red[NSTATES];
    int t = threadIdx.x;
    float x = pr[t];
    red[t] = x; __syncthreads();
    for (int s = 256; s > 0; s >>= 1) { if (t < s) red[t] = fmaxf(red[t], red[t+s]); __syncthreads(); }
    float m = red[0]; __syncthreads();
    red[t] = __expf(x - m); __syncthreads();
    for (int s = 256; s > 0; s >>= 1) { if (t < s) red[t] += red[t+s]; __syncthreads(); }
    gLP[t] = x - (m + __logf(red[0]));
}

// ---------------- grid barrier (all NB CTAs resident) ----------------
__device__ __forceinline__ void gridbar(unsigned target) {
    __syncthreads();
    if (threadIdx.x == 0) {
        __threadfence();                 // release my CTA's writes
        atomicAdd(&g_cnt, 1u);
        while (*(volatile unsigned*)&g_cnt < target) { __nanosleep(64); }
        __threadfence();                 // acquire others' writes
    }
    __syncthreads();
}

// ---------------- publish new alpha tile (tile-normalized) ----------------
__device__ __forceinline__ void produce(int q, int j, int gb0, int gb1, int ig0, int ig1,
                                        float v00, float v01, float v10, float v11) {
    // half-warp (16-lane) reductions: lanes 0..15 own one b, 16..31 own another
    float m0 = fmaxf(v00, v01);
    float m1 = fmaxf(v10, v11);
    #pragma unroll
    for (int o = 8; o > 0; o >>= 1) {
        m0 = fmaxf(m0, __shfl_xor_sync(0xffffffffu, m0, o));
        m1 = fmaxf(m1, __shfl_xor_sync(0xffffffffu, m1, o));
    }
    float e00 = __expf(v00 - m0), e01 = __expf(v01 - m0);
    float e10 = __expf(v10 - m1), e11 = __expf(v11 - m1);
    float s0 = e00 + e01, s1 = e10 + e11;
    #pragma unroll
    for (int o = 8; o > 0; o >>= 1) {
        s0 += __shfl_xor_sync(0xffffffffu, s0, o);
        s1 += __shfl_xor_sync(0xffffffffu, s1, o);
    }
    gE[q][gb0][ig0] = e00; gE[q][gb0][ig1] = e01;
    gE[q][gb1][ig0] = e10; gE[q][gb1][ig1] = e11;
    if ((threadIdx.x & 15) == 0) {
        gM[q][gb0][j] = m0; gS[q][gb0][j] = s0;
        gM[q][gb1][j] = m1; gS[q][gb1][j] = s1;
    }
}

// ---------------- persistent forward kernel ----------------
extern __shared__ float sm_raw[];

__global__ void __launch_bounds__(NT, 1) forward_kernel(const int* __restrict__ batch,
                                                        float* __restrict__ out) {
    float* P_s   = sm_raw;                        // [IC][PSTR]
    float* E_s   = P_s + IC * PSTR;               // [BC][ESTR]
    float* syms_f= E_s + BC * ESTR;               // [BC][TLEN] (ints)
    int*   syms  = (int*)syms_f;
    float* m_sh  = syms_f + BC * TLEN;            // [BC]
    float* sc_sh = m_sh + BC;                     // [BC][GI]

    const int cta = blockIdx.x;
    const int g   = cta / GI;      // batch group
    const int j   = cta % GI;      // i tile
    const int tid = threadIdx.x;
    const int b_idx = tid >> 4;    // 0..15
    const int i_idx = tid & 15;    // 0..15
    const int b0 = b_idx, b1 = b_idx + 16;
    const int i0 = i_idx, i1 = i_idx + 16;
    const int gb0 = g * BC + b0, gb1 = g * BC + b1;
    const int ig0 = j * IC + i0, ig1 = j * IC + i1;

    // load P tile once (resident for all 255 steps)
    for (int idx = tid; idx < IC * NSTATES; idx += NT) {
        int il = idx >> 9, k = idx & (NSTATES - 1);
        P_s[il * PSTR + k] = gP[(j * IC + il) * NSTATES + k];
    }
    // load my symbol rows once
    for (int idx = tid; idx < BC * TLEN; idx += NT) {
        int bl = idx >> 8, t = idx & (TLEN - 1);
        syms[bl * TLEN + t] = batch[(g * BC + bl) * TLEN + t];
    }
    __syncthreads();

    // ---- step 0: alpha0 = em(:,0,:) + priors
    {
        int s0 = syms[b0 * TLEN + 0];
        int s1 = syms[b1 * TLEN + 0];
        float lp0 = gLP[ig0], lp1 = gLP[ig1];
        float v00 = gLET[s0 * NSTATES + ig0] + lp0;
        float v01 = gLET[s0 * NSTATES + ig1] + lp1;
        float v10 = gLET[s1 * NSTATES + ig0] + lp0;
        float v11 = gLET[s1 * NSTATES + ig1] + lp1;
        produce(0, j, gb0, gb1, ig0, ig1, v00, v01, v10, v11);
    }
    unsigned target = NB;
    gridbar(target);

    const float* pe0 = &E_s[b0 * ESTR];
    const float* pe1 = &E_s[b1 * ESTR];
    const float* pp0 = &P_s[i0 * PSTR];
    const float* pp1 = &P_s[i1 * PSTR];

    for (int t = 1; t < TLEN; ++t) {
        const int p = (t - 1) & 1, q = t & 1;

        // phase 1: per-b global max + per-segment rescale factors
        if (tid < BC) {
            float tmp[GI];
            float mb = -__int_as_float(0x7f800000) * 0.0f - 1e30f; // -inf-ish
            mb = -1e30f;
            #pragma unroll
            for (int jj = 0; jj < GI; jj++) {
                tmp[jj] = gM[p][g * BC + tid][jj];
                mb = fmaxf(mb, tmp[jj]);
            }
            m_sh[tid] = mb;
            #pragma unroll
            for (int jj = 0; jj < GI; jj++)
                sc_sh[tid * GI + jj] = __expf(tmp[jj] - mb);
        }
        __syncthreads();

        // phase 1b: stage E rows (rescaled to the global per-b max) into SMEM
        for (int idx = tid; idx < BC * (NSTATES / 4); idx += NT) {
            int bl = idx >> 7;          // NSTATES/4 = 128
            int k4 = idx & 127;
            float4 e = ((const float4*)gE[p][g * BC + bl])[k4];
            float sc = sc_sh[bl * GI + (k4 >> 3)];   // segment = (4*k4)/32
            e.x *= sc; e.y *= sc; e.z *= sc; e.w *= sc;
            ((float4*)&E_s[bl * ESTR])[k4] = e;
        }
        __syncthreads();

        // phase 2: emit output for step t-1 (i-tile 0 CTAs own it)
        if (j == 0 && tid < BC) {
            float ssum = 0.f;
            #pragma unroll
            for (int jj = 0; jj < GI; jj++)
                ssum += sc_sh[tid * GI + jj] * gS[p][g * BC + tid][jj];
            out[(g * BC + tid) * TLEN + (t - 1)] = m_sh[tid] + __logf(ssum);
        }

        // phase 3: contraction  a[b][i] = sum_k P[i][k] * E[b][k]
        float a00 = 0.f, a01 = 0.f, a10 = 0.f, a11 = 0.f;
        #pragma unroll 4
        for (int k = 0; k < NSTATES; k += 4) {
            float4 e0 = *(const float4*)(pe0 + k);
            float4 e1 = *(const float4*)(pe1 + k);
            float4 q0 = *(const float4*)(pp0 + k);
            float4 q1 = *(const float4*)(pp1 + k);
            a00 = fmaf(e0.x, q0.x, a00); a00 = fmaf(e0.y, q0.y, a00);
            a00 = fmaf(e0.z, q0.z, a00); a00 = fmaf(e0.w, q0.w, a00);
            a01 = fmaf(e0.x, q1.x, a01); a01 = fmaf(e0.y, q1.y, a01);
            a01 = fmaf(e0.z, q1.z, a01); a01 = fmaf(e0.w, q1.w, a01);
            a10 = fmaf(e1.x, q0.x, a10); a10 = fmaf(e1.y, q0.y, a10);
            a10 = fmaf(e1.z, q0.z, a10); a10 = fmaf(e1.w, q0.w, a10);
            a11 = fmaf(e1.x, q1.x, a11); a11 = fmaf(e1.y, q1.y, a11);
            a11 = fmaf(e1.z, q1.z, a11); a11 = fmaf(e1.w, q1.w, a11);
        }

        // phase 4: back to log space + emission gather
        float mb0 = m_sh[b0], mb1 = m_sh[b1];
        int s0 = syms[b0 * TLEN + t];
        int s1 = syms[b1 * TLEN + t];
        float v00 = __logf(a00) + mb0 + gLET[s0 * NSTATES + ig0];
        float v01 = __logf(a01) + mb0 + gLET[s0 * NSTATES + ig1];
        float v10 = __logf(a10) + mb1 + gLET[s1 * NSTATES + ig0];
        float v11 = __logf(a11) + mb1 + gLET[s1 * NSTATES + ig1];

        // phase 5: publish new alpha tile (buffer q)
        produce(q, j, gb0, gb1, ig0, ig1, v00, v01, v10, v11);

        target += NB;
        gridbar(target);
    }

    // final output column t = TLEN-1 (buffer (TLEN-1)&1 == 1)
    if (j == 0 && tid < BC) {
        const int p = (TLEN - 1) & 1;
        float tmp[GI];
        float mb = -1e30f;
        #pragma unroll
        for (int jj = 0; jj < GI; jj++) {
            tmp[jj] = gM[p][g * BC + tid][jj];
            mb = fmaxf(mb, tmp[jj]);
        }
        float ssum = 0.f;
        #pragma unroll
        for (int jj = 0; jj < GI; jj++)
            ssum += __expf(tmp[jj] - mb) * gS[p][g * BC + tid][jj];
        out[(g * BC + tid) * TLEN + (TLEN - 1)] = mb + __logf(ssum);
    }
}

// ---------------- launch ----------------
extern "C" void kernel_launch(void* const* d_in, const int* in_sizes, int n_in,
                              void* d_out, int out_size) {
    const int*   batch = (const int*)d_in[0];
    const float* em    = (const float*)d_in[1];
    const float* tr    = (const float*)d_in[2];
    const float* pr    = (const float*)d_in[3];
    float* out = (float*)d_out;

    const size_t smem = (size_t)(IC * PSTR + BC * ESTR + BC * TLEN + BC + BC * GI) * sizeof(float);
    cudaFuncSetAttribute(forward_kernel, cudaFuncAttributeMaxDynamicSharedMemorySize, (int)smem);

    k_prep_emission<<<NSTATES, MSYMS>>>(em);
    k_prep_tstats<<<NSTATES, 256>>>(tr);
    k_prep_P<<<NSTATES, NSTATES>>>(tr);
    k_prep_priors<<<1, NSTATES>>>(pr);
    k_reset<<<1, 1>>>();
    forward_kernel<<<NB, NT, smem>>>(batch, out);
}

// round 3
// speedup vs baseline: 2.8230x; 2.8230x over previous
#include <cuda_runtime.h>
#include <cuda_fp16.h>
#include <cstdint>

#define NSTATES 512
#define MSYMS   256
#define BATCHN  256
#define TLEN    256

#define GB 8                 // batch groups
#define GI 16                // i-slices
#define NCTA (GB*GI)         // 128 CTAs
#define NT 256               // 8 warps

#define ESTR 520             // fp16 row stride (1040B) — conflict-free, 16B aligned

// ---- dynamic SMEM layout (bytes) ----
#define MB_OFF    0                      // float[32]
#define SC_OFF    128                    // float[32][16]
#define BUF_OFF   2176                   // float[8][16][18] = 9216B
#define P_OFF     11392                  // 32 x 520 fp16 = 33280B
#define E_OFF     44672                  // 32 x 520 fp16 = 33280B
#define SYMS_OFF  77952                  // 32 x 256 int  = 32768B
#define SMEM_TOTAL 110720

// ---------------- device globals ----------------
__device__ __half gPh[NSTATES * NSTATES];   // column-softmax of transition, fp16
__device__ float  gLET[MSYMS * NSTATES];    // log emission transposed [sym][state]
__device__ float  gLP[NSTATES];             // log priors
__device__ float  gColLse[NSTATES];
__device__ __half gEh[2][BATCHN][NSTATES];  // exp(alpha - tile_max), fp16, dbl-buffered
__device__ float  gM2[2][BATCHN][GI];       // per (b, i-tile) max
__device__ float  gS2[2][BATCHN][GI];       // per (b, i-tile) sum
__device__ unsigned g_cnt;

// ---------------- PTX helpers (baseline ISA only) ----------------
__device__ __forceinline__ uint32_t smem_u32(const void* p) {
    uint32_t a;
    asm("{ .reg .u64 t; cvta.to.shared.u64 t, %1; cvt.u32.u64 %0, t; }" : "=r"(a) : "l"(p));
    return a;
}
__device__ __forceinline__ void ldsm4(uint32_t& r0, uint32_t& r1, uint32_t& r2, uint32_t& r3,
                                      uint32_t addr) {
    asm volatile("ldmatrix.sync.aligned.m8n8.x4.shared.b16 {%0,%1,%2,%3}, [%4];"
                 : "=r"(r0), "=r"(r1), "=r"(r2), "=r"(r3) : "r"(addr));
}
__device__ __forceinline__ void mma16816(float& d0, float& d1, float& d2, float& d3,
                                         uint32_t a0, uint32_t a1, uint32_t a2, uint32_t a3,
                                         uint32_t b0, uint32_t b1) {
    asm volatile(
        "mma.sync.aligned.m16n8k16.row.col.f32.f16.f16.f32 "
        "{%0,%1,%2,%3}, {%4,%5,%6,%7}, {%8,%9}, {%0,%1,%2,%3};"
        : "+f"(d0), "+f"(d1), "+f"(d2), "+f"(d3)
        : "r"(a0), "r"(a1), "r"(a2), "r"(a3), "r"(b0), "r"(b1));
}

// ---------------- prep kernels ----------------
__global__ void k_reset() { g_cnt = 0u; }

__global__ void k_prep_emission(const float* __restrict__ em) {
    __shared__ float red[MSYMS];
    int n = blockIdx.x, t = threadIdx.x;
    float x = em[n * MSYMS + t];
    red[t] = x; __syncthreads();
    for (int s = MSYMS / 2; s > 0; s >>= 1) { if (t < s) red[t] = fmaxf(red[t], red[t + s]); __syncthreads(); }
    float m = red[0]; __syncthreads();
    red[t] = __expf(x - m); __syncthreads();
    for (int s = MSYMS / 2; s > 0; s >>= 1) { if (t < s) red[t] += red[t + s]; __syncthreads(); }
    float lse = m + __logf(red[0]);
    gLET[t * NSTATES + n] = x - lse;
}

__global__ void k_prep_tstats(const float* __restrict__ tr) {
    __shared__ float red[256];
    int k = blockIdx.x, t = threadIdx.x;
    float x0 = tr[t * NSTATES + k];
    float x1 = tr[(t + 256) * NSTATES + k];
    red[t] = fmaxf(x0, x1); __syncthreads();
    for (int s = 128; s > 0; s >>= 1) { if (t < s) red[t] = fmaxf(red[t], red[t + s]); __syncthreads(); }
    float m = red[0]; __syncthreads();
    red[t] = __expf(x0 - m) + __expf(x1 - m); __syncthreads();
    for (int s = 128; s > 0; s >>= 1) { if (t < s) red[t] += red[t + s]; __syncthreads(); }
    if (t == 0) gColLse[k] = m + __logf(red[0]);
}

__global__ void k_prep_P(const float* __restrict__ tr) {
    int i = blockIdx.x, k = threadIdx.x;
    gPh[i * NSTATES + k] = __float2half_rn(__expf(tr[i * NSTATES + k] - gColLse[k]));
}

__global__ void k_prep_priors(const float* __restrict__ pr) {
    __shared__ float red[NSTATES];
    int t = threadIdx.x;
    float x = pr[t];
    red[t] = x; __syncthreads();
    for (int s = 256; s > 0; s >>= 1) { if (t < s) red[t] = fmaxf(red[t], red[t + s]); __syncthreads(); }
    float m = red[0]; __syncthreads();
    red[t] = __expf(x - m); __syncthreads();
    for (int s = 256; s > 0; s >>= 1) { if (t < s) red[t] += red[t + s]; __syncthreads(); }
    gLP[t] = x - (m + __logf(red[0]));
}

// ---------------- grid barrier ----------------
__device__ __forceinline__ void gridbar(unsigned target) {
    __syncthreads();
    if (threadIdx.x == 0) {
        __threadfence();
        atomicAdd(&g_cnt, 1u);
        while (*(volatile unsigned*)&g_cnt < target) { __nanosleep(16); }
        __threadfence();
    }
    __syncthreads();
}

// ---------------- forward kernel ----------------
extern __shared__ char sm_raw[];

__global__ void __launch_bounds__(NT, 1) forward_kernel(const int* __restrict__ batch,
                                                        float* __restrict__ out) {
    char* sm = sm_raw;
    const uint32_t smem_base = smem_u32(sm);
    float* sm_mb = (float*)(sm + MB_OFF);       // [32]
    float* sm_sc = (float*)(sm + SC_OFF);       // [32][16]
    float* buf   = (float*)(sm + BUF_OFF);      // [8][16][18]
    int*   syms  = (int*)(sm + SYMS_OFF);       // [32][256]
    const uint32_t P_base = smem_base + P_OFF;
    const uint32_t E_base = smem_base + E_OFF;

    const int tid  = threadIdx.x;
    const int lane = tid & 31;
    const int w    = tid >> 5;
    const int g    = blockIdx.x >> 4;   // 0..7 batch group
    const int j    = blockIdx.x & 15;   // 0..15 i-slice

    // epilogue/staging mapping: thread owns (b, i4..i4+3)
    const int b  = tid >> 3;            // 0..31
    const int i4 = (tid & 7) * 4;       // 0,4,...,28
    const int gb = g * 32 + b;

    // warp tile decomposition: m16 x n16 x k256
    const int mi = w & 1, ni = (w >> 1) & 1, kh = (w >> 2) & 1;
    const int kbase = kh * 256;

    // ---------------- prologue ----------------
    // P j-slice -> SMEM (padded rows)
    {
        const __half* src = &gPh[(j * 32 + (tid >> 3)) * NSTATES];
        char* dst = sm + P_OFF + (tid >> 3) * (ESTR * 2);
        #pragma unroll
        for (int u = 0; u < 8; u++) {
            int c = (tid & 7) + 8 * u;                    // 16B chunk 0..63
            *(uint4*)(dst + c * 16) = *(const uint4*)(src + c * 8);
        }
    }
    // symbols
    for (int idx = tid; idx < 32 * TLEN; idx += NT)
        syms[idx] = batch[(g * 32 + (idx >> 8)) * TLEN + (idx & 255)];
    __syncthreads();

    // A fragments resident in registers for all steps
    uint32_t a[16][4];
    {
        const int arow  = mi * 16 + (lane & 15);
        const int akoff = (lane >> 4) * 8;
        #pragma unroll
        for (int kk = 0; kk < 16; kk++) {
            uint32_t addr = P_base + (uint32_t)((arow * ESTR + kbase + kk * 16 + akoff) * 2);
            ldsm4(a[kk][0], a[kk][1], a[kk][2], a[kk][3], addr);
        }
    }

    // B ldmatrix address base (row/col components fixed per thread)
    const int brow = ni * 16 + (lane >> 4) * 8 + (lane & 7);
    const int bk0  = ((lane >> 3) & 1) * 8 + kbase;
    const uint32_t b_addr0 = E_base + (uint32_t)((brow * ESTR + bk0) * 2);

    unsigned target = NCTA;

    // ---------------- step 0 ----------------
    {
        int sy = syms[b * TLEN + 0];
        float4 lt = *(const float4*)&gLET[sy * NSTATES + j * 32 + i4];
        float4 lp = *(const float4*)&gLP[j * 32 + i4];
        float v0 = lt.x + lp.x, v1 = lt.y + lp.y, v2 = lt.z + lp.z, v3 = lt.w + lp.w;
        float m = fmaxf(fmaxf(v0, v1), fmaxf(v2, v3));
        #pragma unroll
        for (int o = 4; o > 0; o >>= 1) m = fmaxf(m, __shfl_xor_sync(0xffffffffu, m, o));
        float e0 = __expf(v0 - m), e1 = __expf(v1 - m), e2 = __expf(v2 - m), e3 = __expf(v3 - m);
        float s = e0 + e1 + e2 + e3;
        #pragma unroll
        for (int o = 4; o > 0; o >>= 1) s += __shfl_xor_sync(0xffffffffu, s, o);
        union { __half2 h[2]; uint2 u; } cv;
        cv.h[0] = __floats2half2_rn(e0, e1);
        cv.h[1] = __floats2half2_rn(e2, e3);
        *(uint2*)&gEh[0][gb][j * 32 + i4] = cv.u;
        if ((tid & 7) == 0) { gM2[0][gb][j] = m; gS2[0][gb][j] = s; }
        gridbar(target); target += NCTA;
    }

    // ---------------- main loop ----------------
    for (int t = 1; t < TLEN; ++t) {
        const int p = (t - 1) & 1, q = t & 1;

        // phase 1: per-b global max + 16 tile scales (+ output col t-1 on j==0)
        if (tid < 32) {
            int gbb = g * 32 + tid;
            const float* mrow = &gM2[p][gbb][0];
            float mv[16];
            float4 f;
            f = *(const float4*)(mrow + 0);  mv[0]=f.x; mv[1]=f.y; mv[2]=f.z; mv[3]=f.w;
            f = *(const float4*)(mrow + 4);  mv[4]=f.x; mv[5]=f.y; mv[6]=f.z; mv[7]=f.w;
            f = *(const float4*)(mrow + 8);  mv[8]=f.x; mv[9]=f.y; mv[10]=f.z; mv[11]=f.w;
            f = *(const float4*)(mrow + 12); mv[12]=f.x; mv[13]=f.y; mv[14]=f.z; mv[15]=f.w;
            float mb = mv[0];
            #pragma unroll
            for (int jj = 1; jj < 16; jj++) mb = fmaxf(mb, mv[jj]);
            sm_mb[tid] = mb;
            float sc[16];
            #pragma unroll
            for (int jj = 0; jj < 16; jj++) { sc[jj] = __expf(mv[jj] - mb); sm_sc[tid * 16 + jj] = sc[jj]; }
            if (j == 0) {
                const float* srow = &gS2[p][gbb][0];
                float ssum = 0.f;
                #pragma unroll
                for (int jj = 0; jj < 16; jj++) ssum += sc[jj] * srow[jj];
                out[gbb * TLEN + (t - 1)] = mb + __logf(ssum);
            }
        }
        __syncthreads();

        // prefetch emission row + per-b max
        int sy = syms[b * TLEN + t];
        float4 lt = *(const float4*)&gLET[sy * NSTATES + j * 32 + i4];
        float mbv = sm_mb[b];

        // phase 2: stage E (rescaled, fp16) into padded SMEM
        {
            const __half* esrc = &gEh[p][gb][0];
            char* edst = sm + E_OFF + b * (ESTR * 2);
            #pragma unroll
            for (int u = 0; u < 8; u++) {
                int c = (tid & 7) + 8 * u;                 // 8-half chunk, k = c*8
                float sc = sm_sc[b * 16 + (c >> 2)];       // tile = k>>5 = c>>2
                uint4 raw = *(const uint4*)(esrc + c * 8);
                __half2* hp = (__half2*)&raw;
                #pragma unroll
                for (int z = 0; z < 4; z++) {
                    float2 f2 = __half22float2(hp[z]);
                    hp[z] = __floats2half2_rn(f2.x * sc, f2.y * sc);
                }
                *(uint4*)(edst + c * 16) = raw;
            }
        }
        __syncthreads();

        // phase 3: HMMA contraction (A in regs, B from SMEM)
        float d0 = 0.f, d1 = 0.f, d2 = 0.f, d3 = 0.f;
        float d4 = 0.f, d5 = 0.f, d6 = 0.f, d7 = 0.f;
        #pragma unroll
        for (int kk = 0; kk < 16; kk++) {
            uint32_t r0, r1, r2, r3;
            ldsm4(r0, r1, r2, r3, b_addr0 + (uint32_t)(kk * 32));  // +16 halfs
            mma16816(d0, d1, d2, d3, a[kk][0], a[kk][1], a[kk][2], a[kk][3], r0, r1);
            mma16816(d4, d5, d6, d7, a[kk][0], a[kk][1], a[kk][2], a[kk][3], r2, r3);
        }

        // phase 4: stash partials
        {
            int r1r = lane >> 2, c0 = (lane & 3) * 2;
            float* bw = &buf[w * 16 * 18];
            *(float2*)&bw[r1r * 18 + c0]           = make_float2(d0, d1);
            *(float2*)&bw[(r1r + 8) * 18 + c0]     = make_float2(d2, d3);
            *(float2*)&bw[r1r * 18 + c0 + 8]       = make_float2(d4, d5);
            *(float2*)&bw[(r1r + 8) * 18 + c0 + 8] = make_float2(d6, d7);
        }
        __syncthreads();

        // phase 5: epilogue — split-k add, log, +mb+em, publish
        {
            const int nib = b >> 4, cb = b & 15;
            const int mis = i4 >> 4, rbase = i4 & 15;
            const float* b0p = &buf[(mis + 2 * nib) * 288 + cb];
            const float* b1p = b0p + 4 * 288;
            float C0 = b0p[(rbase + 0) * 18] + b1p[(rbase + 0) * 18];
            float C1 = b0p[(rbase + 1) * 18] + b1p[(rbase + 1) * 18];
            float C2 = b0p[(rbase + 2) * 18] + b1p[(rbase + 2) * 18];
            float C3 = b0p[(rbase + 3) * 18] + b1p[(rbase + 3) * 18];
            float v0 = __logf(C0) + mbv + lt.x;
            float v1 = __logf(C1) + mbv + lt.y;
            float v2 = __logf(C2) + mbv + lt.z;
            float v3 = __logf(C3) + mbv + lt.w;
            float m = fmaxf(fmaxf(v0, v1), fmaxf(v2, v3));
            #pragma unroll
            for (int o = 4; o > 0; o >>= 1) m = fmaxf(m, __shfl_xor_sync(0xffffffffu, m, o));
            float e0 = __expf(v0 - m), e1 = __expf(v1 - m), e2 = __expf(v2 - m), e3 = __expf(v3 - m);
            float s = e0 + e1 + e2 + e3;
            #pragma unroll
            for (int o = 4; o > 0; o >>= 1) s += __shfl_xor_sync(0xffffffffu, s, o);
            union { __half2 h[2]; uint2 u; } cv;
            cv.h[0] = __floats2half2_rn(e0, e1);
            cv.h[1] = __floats2half2_rn(e2, e3);
            *(uint2*)&gEh[q][gb][j * 32 + i4] = cv.u;
            if ((tid & 7) == 0) { gM2[q][gb][j] = m; gS2[q][gb][j] = s; }
        }

        gridbar(target); target += NCTA;
    }

    // final output column t = 255 (buffer 1)
    if (j == 0 && tid < 32) {
        const int p = (TLEN - 1) & 1;
        int gbb = g * 32 + tid;
        const float* mrow = &gM2[p][gbb][0];
        const float* srow = &gS2[p][gbb][0];
        float mb = mrow[0];
        #pragma unroll
        for (int jj = 1; jj < 16; jj++) mb = fmaxf(mb, mrow[jj]);
        float ssum = 0.f;
        #pragma unroll
        for (int jj = 0; jj < 16; jj++) ssum += __expf(mrow[jj] - mb) * srow[jj];
        out[gbb * TLEN + (TLEN - 1)] = mb + __logf(ssum);
    }
}

// ---------------- launch ----------------
extern "C" void kernel_launch(void* const* d_in, const int* in_sizes, int n_in,
                              void* d_out, int out_size) {
    const int*   batch = (const int*)d_in[0];
    const float* em    = (const float*)d_in[1];
    const float* tr    = (const float*)d_in[2];
    const float* pr    = (const float*)d_in[3];
    float* out = (float*)d_out;

    cudaFuncSetAttribute(forward_kernel, cudaFuncAttributeMaxDynamicSharedMemorySize, SMEM_TOTAL);

    k_prep_emission<<<NSTATES, MSYMS>>>(em);
    k_prep_tstats<<<NSTATES, 256>>>(tr);
    k_prep_P<<<NSTATES, NSTATES>>>(tr);
    k_prep_priors<<<1, NSTATES>>>(pr);
    k_reset<<<1, 1>>>();
    forward_kernel<<<NCTA, NT, SMEM_TOTAL>>>(batch, out);
}

// round 4
// speedup vs baseline: 3.0662x; 1.0862x over previous
#include <cuda_runtime.h>
#include <cuda_fp16.h>
#include <cstdint>

#define NSTATES 512
#define MSYMS   256
#define BATCHN  256
#define TLEN    256

#define GB 8                 // batch groups
#define GI 16                // i-slices
#define NCTA (GB*GI)         // 128 CTAs
#define NT 256               // 8 warps

#define ESTR 520             // fp16 row stride (1040B) — conflict-free, 16B aligned

// ---- dynamic SMEM layout (bytes) ----
#define MB_OFF    0                      // float[32]
#define SC_OFF    128                    // float[32][16]
#define BUF_OFF   2176                   // float[8][16][18] = 9216B
#define P_OFF     11392                  // 32 x 520 fp16 = 33280B
#define E_OFF     44672                  // 32 x 520 fp16 = 33280B
#define SYMS_OFF  77952                  // 32 x 256 int  = 32768B
#define SMEM_TOTAL 110720

// ---------------- device globals ----------------
__device__ __half gPh[NSTATES * NSTATES];   // column-softmax of transition, fp16
__device__ float  gLET[MSYMS * NSTATES];    // log emission transposed [sym][state]
__device__ float  gLP[NSTATES];             // log priors
__device__ float  gColLse[NSTATES];
__device__ __half gEh[2][BATCHN][NSTATES];  // exp(alpha - tile_max), fp16, dbl-buffered
__device__ float  gM2[2][BATCHN][GI];       // per (b, i-tile) max
__device__ float  gS2[2][BATCHN][GI];       // per (b, i-tile) sum
__device__ unsigned g_cnt_arr[GB * 32];     // one barrier counter per batch group, 128B apart

// ---------------- PTX helpers (baseline ISA only) ----------------
__device__ __forceinline__ uint32_t smem_u32(const void* p) {
    uint32_t a;
    asm("{ .reg .u64 t; cvta.to.shared.u64 t, %1; cvt.u32.u64 %0, t; }" : "=r"(a) : "l"(p));
    return a;
}
__device__ __forceinline__ void ldsm4(uint32_t& r0, uint32_t& r1, uint32_t& r2, uint32_t& r3,
                                      uint32_t addr) {
    asm volatile("ldmatrix.sync.aligned.m8n8.x4.shared.b16 {%0,%1,%2,%3}, [%4];"
                 : "=r"(r0), "=r"(r1), "=r"(r2), "=r"(r3) : "r"(addr));
}
__device__ __forceinline__ void mma16816(float& d0, float& d1, float& d2, float& d3,
                                         uint32_t a0, uint32_t a1, uint32_t a2, uint32_t a3,
                                         uint32_t b0, uint32_t b1) {
    asm volatile(
        "mma.sync.aligned.m16n8k16.row.col.f32.f16.f16.f32 "
        "{%0,%1,%2,%3}, {%4,%5,%6,%7}, {%8,%9}, {%0,%1,%2,%3};"
        : "+f"(d0), "+f"(d1), "+f"(d2), "+f"(d3)
        : "r"(a0), "r"(a1), "r"(a2), "r"(a3), "r"(b0), "r"(b1));
}

// ---------------- prep kernels ----------------
__global__ void k_reset() { if (threadIdx.x < GB) g_cnt_arr[threadIdx.x * 32] = 0u; }

__global__ void k_prep_emission(const float* __restrict__ em) {
    __shared__ float red[MSYMS];
    int n = blockIdx.x, t = threadIdx.x;
    float x = em[n * MSYMS + t];
    red[t] = x; __syncthreads();
    for (int s = MSYMS / 2; s > 0; s >>= 1) { if (t < s) red[t] = fmaxf(red[t], red[t + s]); __syncthreads(); }
    float m = red[0]; __syncthreads();
    red[t] = __expf(x - m); __syncthreads();
    for (int s = MSYMS / 2; s > 0; s >>= 1) { if (t < s) red[t] += red[t + s]; __syncthreads(); }
    float lse = m + __logf(red[0]);
    gLET[t * NSTATES + n] = x - lse;
}

__global__ void k_prep_tstats(const float* __restrict__ tr) {
    __shared__ float red[256];
    int k = blockIdx.x, t = threadIdx.x;
    float x0 = tr[t * NSTATES + k];
    float x1 = tr[(t + 256) * NSTATES + k];
    red[t] = fmaxf(x0, x1); __syncthreads();
    for (int s = 128; s > 0; s >>= 1) { if (t < s) red[t] = fmaxf(red[t], red[t + s]); __syncthreads(); }
    float m = red[0]; __syncthreads();
    red[t] = __expf(x0 - m) + __expf(x1 - m); __syncthreads();
    for (int s = 128; s > 0; s >>= 1) { if (t < s) red[t] += red[t + s]; __syncthreads(); }
    if (t == 0) gColLse[k] = m + __logf(red[0]);
}

__global__ void k_prep_P(const float* __restrict__ tr) {
    int i = blockIdx.x, k = threadIdx.x;
    gPh[i * NSTATES + k] = __float2half_rn(__expf(tr[i * NSTATES + k] - gColLse[k]));
}

__global__ void k_prep_priors(const float* __restrict__ pr) {
    __shared__ float red[NSTATES];
    int t = threadIdx.x;
    float x = pr[t];
    red[t] = x; __syncthreads();
    for (int s = 256; s > 0; s >>= 1) { if (t < s) red[t] = fmaxf(red[t], red[t + s]); __syncthreads(); }
    float m = red[0]; __syncthreads();
    red[t] = __expf(x - m); __syncthreads();
    for (int s = 256; s > 0; s >>= 1) { if (t < s) red[t] += red[t + s]; __syncthreads(); }
    gLP[t] = x - (m + __logf(red[0]));
}

// ---------------- per-group barrier (16 CTAs per group) ----------------
__device__ __forceinline__ void groupbar(unsigned* cnt, unsigned target) {
    __syncthreads();
    if (threadIdx.x == 0) {
        __threadfence();
        atomicAdd(cnt, 1u);
        while (*(volatile unsigned*)cnt < target) { }
        __threadfence();
    }
    __syncthreads();
}

// ---------------- forward kernel ----------------
extern __shared__ char sm_raw[];

__global__ void __launch_bounds__(NT, 1) forward_kernel(const int* __restrict__ batch,
                                                        float* __restrict__ out) {
    char* sm = sm_raw;
    const uint32_t smem_base = smem_u32(sm);
    float* sm_mb = (float*)(sm + MB_OFF);       // [32]
    float* sm_sc = (float*)(sm + SC_OFF);       // [32][16]
    float* buf   = (float*)(sm + BUF_OFF);      // [8][16][18]
    int*   syms  = (int*)(sm + SYMS_OFF);       // [32][256]
    const uint32_t P_base = smem_base + P_OFF;
    const uint32_t E_base = smem_base + E_OFF;

    const int tid  = threadIdx.x;
    const int lane = tid & 31;
    const int w    = tid >> 5;
    const int g    = blockIdx.x >> 4;   // 0..7 batch group
    const int j    = blockIdx.x & 15;   // 0..15 i-slice
    unsigned* my_cnt = &g_cnt_arr[g * 32];

    // epilogue/staging mapping: thread owns (b, i4..i4+3)
    const int b  = tid >> 3;            // 0..31
    const int i4 = (tid & 7) * 4;       // 0,4,...,28
    const int gb = g * 32 + b;

    // warp tile decomposition: m16 x n16 x k256
    const int mi = w & 1, ni = (w >> 1) & 1, kh = (w >> 2) & 1;
    const int kbase = kh * 256;

    // ---------------- prologue ----------------
    // P j-slice -> SMEM (padded rows)
    {
        const __half* src = &gPh[(j * 32 + (tid >> 3)) * NSTATES];
        char* dst = sm + P_OFF + (tid >> 3) * (ESTR * 2);
        #pragma unroll
        for (int u = 0; u < 8; u++) {
            int c = (tid & 7) + 8 * u;                    // 16B chunk 0..63
            *(uint4*)(dst + c * 16) = *(const uint4*)(src + c * 8);
        }
    }
    // symbols
    for (int idx = tid; idx < 32 * TLEN; idx += NT)
        syms[idx] = batch[(g * 32 + (idx >> 8)) * TLEN + (idx & 255)];
    __syncthreads();

    // A fragments resident in registers for all steps
    uint32_t a[16][4];
    {
        const int arow  = mi * 16 + (lane & 15);
        const int akoff = (lane >> 4) * 8;
        #pragma unroll
        for (int kk = 0; kk < 16; kk++) {
            uint32_t addr = P_base + (uint32_t)((arow * ESTR + kbase + kk * 16 + akoff) * 2);
            ldsm4(a[kk][0], a[kk][1], a[kk][2], a[kk][3], addr);
        }
    }

    // B ldmatrix address base (row/col components fixed per thread)
    const int brow = ni * 16 + (lane >> 4) * 8 + (lane & 7);
    const int bk0  = ((lane >> 3) & 1) * 8 + kbase;
    const uint32_t b_addr0 = E_base + (uint32_t)((brow * ESTR + bk0) * 2);

    unsigned target = GI;

    // ---------------- step 0 ----------------
    {
        int sy = syms[b * TLEN + 0];
        float4 lt = *(const float4*)&gLET[sy * NSTATES + j * 32 + i4];
        float4 lp = *(const float4*)&gLP[j * 32 + i4];
        float v0 = lt.x + lp.x, v1 = lt.y + lp.y, v2 = lt.z + lp.z, v3 = lt.w + lp.w;
        float m = fmaxf(fmaxf(v0, v1), fmaxf(v2, v3));
        #pragma unroll
        for (int o = 4; o > 0; o >>= 1) m = fmaxf(m, __shfl_xor_sync(0xffffffffu, m, o));
        float e0 = __expf(v0 - m), e1 = __expf(v1 - m), e2 = __expf(v2 - m), e3 = __expf(v3 - m);
        float s = e0 + e1 + e2 + e3;
        #pragma unroll
        for (int o = 4; o > 0; o >>= 1) s += __shfl_xor_sync(0xffffffffu, s, o);
        union { __half2 h[2]; uint2 u; } cv;
        cv.h[0] = __floats2half2_rn(e0, e1);
        cv.h[1] = __floats2half2_rn(e2, e3);
        *(uint2*)&gEh[0][gb][j * 32 + i4] = cv.u;
        if ((tid & 7) == 0) { gM2[0][gb][j] = m; gS2[0][gb][j] = s; }
        groupbar(my_cnt, target); target += GI;
    }

    // ---------------- main loop ----------------
    for (int t = 1; t < TLEN; ++t) {
        const int p = (t - 1) & 1, q = t & 1;

        // phase 0: issue raw E loads into registers immediately (hide L2 latency
        // under the phase-1 stats dependency chain)
        uint4 eraw[8];
        {
            const __half* esrc = &gEh[p][gb][0];
            #pragma unroll
            for (int u = 0; u < 8; u++) {
                int c = (tid & 7) + 8 * u;
                eraw[u] = *(const uint4*)(esrc + c * 8);
            }
        }

        // phase 1: per-b global max + 16 tile scales (+ output col t-1 on j==0)
        if (tid < 32) {
            int gbb = g * 32 + tid;
            const float* mrow = &gM2[p][gbb][0];
            float mv[16];
            float4 f;
            f = *(const float4*)(mrow + 0);  mv[0]=f.x; mv[1]=f.y; mv[2]=f.z; mv[3]=f.w;
            f = *(const float4*)(mrow + 4);  mv[4]=f.x; mv[5]=f.y; mv[6]=f.z; mv[7]=f.w;
            f = *(const float4*)(mrow + 8);  mv[8]=f.x; mv[9]=f.y; mv[10]=f.z; mv[11]=f.w;
            f = *(const float4*)(mrow + 12); mv[12]=f.x; mv[13]=f.y; mv[14]=f.z; mv[15]=f.w;
            float mb = mv[0];
            #pragma unroll
            for (int jj = 1; jj < 16; jj++) mb = fmaxf(mb, mv[jj]);
            sm_mb[tid] = mb;
            float sc[16];
            #pragma unroll
            for (int jj = 0; jj < 16; jj++) { sc[jj] = __expf(mv[jj] - mb); sm_sc[tid * 16 + jj] = sc[jj]; }
            if (j == 0) {
                const float* srow = &gS2[p][gbb][0];
                float ssum = 0.f;
                #pragma unroll
                for (int jj = 0; jj < 16; jj++) ssum += sc[jj] * srow[jj];
                out[gbb * TLEN + (t - 1)] = mb + __logf(ssum);
            }
        }
        __syncthreads();

        // prefetch emission row + per-b max
        int sy = syms[b * TLEN + t];
        float4 lt = *(const float4*)&gLET[sy * NSTATES + j * 32 + i4];
        float mbv = sm_mb[b];

        // phase 2: scale pre-loaded E and store to padded SMEM
        {
            char* edst = sm + E_OFF + b * (ESTR * 2);
            #pragma unroll
            for (int u = 0; u < 8; u++) {
                int c = (tid & 7) + 8 * u;                 // 8-half chunk, k = c*8
                float sc = sm_sc[b * 16 + (c >> 2)];       // tile = k>>5 = c>>2
                uint4 raw = eraw[u];
                __half2* hp = (__half2*)&raw;
                #pragma unroll
                for (int z = 0; z < 4; z++) {
                    float2 f2 = __half22float2(hp[z]);
                    hp[z] = __floats2half2_rn(f2.x * sc, f2.y * sc);
                }
                *(uint4*)(edst + c * 16) = raw;
            }
        }
        __syncthreads();

        // phase 3: HMMA contraction (A in regs, B from SMEM)
        float d0 = 0.f, d1 = 0.f, d2 = 0.f, d3 = 0.f;
        float d4 = 0.f, d5 = 0.f, d6 = 0.f, d7 = 0.f;
        #pragma unroll
        for (int kk = 0; kk < 16; kk++) {
            uint32_t r0, r1, r2, r3;
            ldsm4(r0, r1, r2, r3, b_addr0 + (uint32_t)(kk * 32));  // +16 halfs
            mma16816(d0, d1, d2, d3, a[kk][0], a[kk][1], a[kk][2], a[kk][3], r0, r1);
            mma16816(d4, d5, d6, d7, a[kk][0], a[kk][1], a[kk][2], a[kk][3], r2, r3);
        }

        // phase 4: stash partials
        {
            int r1r = lane >> 2, c0 = (lane & 3) * 2;
            float* bw = &buf[w * 16 * 18];
            *(float2*)&bw[r1r * 18 + c0]           = make_float2(d0, d1);
            *(float2*)&bw[(r1r + 8) * 18 + c0]     = make_float2(d2, d3);
            *(float2*)&bw[r1r * 18 + c0 + 8]       = make_float2(d4, d5);
            *(float2*)&bw[(r1r + 8) * 18 + c0 + 8] = make_float2(d6, d7);
        }
        __syncthreads();

        // phase 5: epilogue — split-k add, log, +mb+em, publish
        {
            const int nib = b >> 4, cb = b & 15;
            const int mis = i4 >> 4, rbase = i4 & 15;
            const float* b0p = &buf[(mis + 2 * nib) * 288 + cb];
            const float* b1p = b0p + 4 * 288;
            float C0 = b0p[(rbase + 0) * 18] + b1p[(rbase + 0) * 18];
            float C1 = b0p[(rbase + 1) * 18] + b1p[(rbase + 1) * 18];
            float C2 = b0p[(rbase + 2) * 18] + b1p[(rbase + 2) * 18];
            float C3 = b0p[(rbase + 3) * 18] + b1p[(rbase + 3) * 18];
            float v0 = __logf(C0) + mbv + lt.x;
            float v1 = __logf(C1) + mbv + lt.y;
            float v2 = __logf(C2) + mbv + lt.z;
            float v3 = __logf(C3) + mbv + lt.w;
            float m = fmaxf(fmaxf(v0, v1), fmaxf(v2, v3));
            #pragma unroll
            for (int o = 4; o > 0; o >>= 1) m = fmaxf(m, __shfl_xor_sync(0xffffffffu, m, o));
            float e0 = __expf(v0 - m), e1 = __expf(v1 - m), e2 = __expf(v2 - m), e3 = __expf(v3 - m);
            float s = e0 + e1 + e2 + e3;
            #pragma unroll
            for (int o = 4; o > 0; o >>= 1) s += __shfl_xor_sync(0xffffffffu, s, o);
            union { __half2 h[2]; uint2 u; } cv;
            cv.h[0] = __floats2half2_rn(e0, e1);
            cv.h[1] = __floats2half2_rn(e2, e3);
            *(uint2*)&gEh[q][gb][j * 32 + i4] = cv.u;
            if ((tid & 7) == 0) { gM2[q][gb][j] = m; gS2[q][gb][j] = s; }
        }

        groupbar(my_cnt, target); target += GI;
    }

    // final output column t = 255 (buffer 1)
    if (j == 0 && tid < 32) {
        const int p = (TLEN - 1) & 1;
        int gbb = g * 32 + tid;
        const float* mrow = &gM2[p][gbb][0];
        const float* srow = &gS2[p][gbb][0];
        float mb = mrow[0];
        #pragma unroll
        for (int jj = 1; jj < 16; jj++) mb = fmaxf(mb, mrow[jj]);
        float ssum = 0.f;
        #pragma unroll
        for (int jj = 0; jj < 16; jj++) ssum += __expf(mrow[jj] - mb) * srow[jj];
        out[gbb * TLEN + (TLEN - 1)] = mb + __logf(ssum);
    }
}

// ---------------- launch ----------------
extern "C" void kernel_launch(void* const* d_in, const int* in_sizes, int n_in,
                              void* d_out, int out_size) {
    const int*   batch = (const int*)d_in[0];
    const float* em    = (const float*)d_in[1];
    const float* tr    = (const float*)d_in[2];
    const float* pr    = (const float*)d_in[3];
    float* out = (float*)d_out;

    cudaFuncSetAttribute(forward_kernel, cudaFuncAttributeMaxDynamicSharedMemorySize, SMEM_TOTAL);

    k_prep_emission<<<NSTATES, MSYMS>>>(em);
    k_prep_tstats<<<NSTATES, 256>>>(tr);
    k_prep_P<<<NSTATES, NSTATES>>>(tr);
    k_prep_priors<<<1, NSTATES>>>(pr);
    k_reset<<<1, 32>>>();
    forward_kernel<<<NCTA, NT, SMEM_TOTAL>>>(batch, out);
}